// round 1
// baseline (speedup 1.0000x reference)
#include <cuda_runtime.h>
#include <math.h>

#define NODES 262144
#define EDGES 2097152

// Scratch (device globals — no runtime allocation allowed)
__device__ __align__(16) float g_y[NODES * 64];     // scaled transformed features (gather source)
__device__ __align__(16) float g_bufA[NODES * 64];  // layer outputs ping
__device__ __align__(16) float g_bufB[NODES * 64];  // layer outputs pong
__device__ int   g_cnt[NODES];     // in-degree counts (excl self loop)
__device__ int   g_row[NODES];     // CSR row offsets
__device__ int   g_cur[NODES];     // scatter cursors
__device__ float g_dinv[NODES];    // rsqrt(deg+1)
__device__ int   g_col[EDGES];     // CSR column (src) indices
__device__ int   g_bsum[512];      // block sums for scan

// ---------------- CSR build ----------------

__global__ void k_zero(int n) {
    int i = blockIdx.x * blockDim.x + threadIdx.x;
    if (i < n) g_cnt[i] = 0;
}

__global__ void k_hist(const int* __restrict__ dst, int e) {
    int i = blockIdx.x * blockDim.x + threadIdx.x;
    if (i < e) atomicAdd(&g_cnt[dst[i]], 1);
}

__global__ void k_scan1(int n) {
    __shared__ int s[512];
    int t = threadIdx.x;
    int idx = blockIdx.x * 512 + t;
    int v = (idx < n) ? g_cnt[idx] : 0;
    s[t] = v;
    __syncthreads();
    #pragma unroll
    for (int off = 1; off < 512; off <<= 1) {
        int a = (t >= off) ? s[t - off] : 0;
        __syncthreads();
        s[t] += a;
        __syncthreads();
    }
    if (idx < n) g_row[idx] = s[t] - v;           // exclusive within block
    if (t == 511) g_bsum[blockIdx.x] = s[511];    // block total
}

__global__ void k_scan2() {
    __shared__ int s[512];
    int t = threadIdx.x;
    int v = g_bsum[t];
    s[t] = v;
    __syncthreads();
    #pragma unroll
    for (int off = 1; off < 512; off <<= 1) {
        int a = (t >= off) ? s[t - off] : 0;
        __syncthreads();
        s[t] += a;
        __syncthreads();
    }
    g_bsum[t] = s[t] - v;                         // exclusive block offsets
}

__global__ void k_fin(int n) {
    int i = blockIdx.x * blockDim.x + threadIdx.x;
    if (i < n) {
        int r = g_row[i] + g_bsum[i >> 9];
        g_row[i] = r;
        g_cur[i] = r;
        g_dinv[i] = rsqrtf((float)(g_cnt[i] + 1));
    }
}

__global__ void k_scatter(const int* __restrict__ src, const int* __restrict__ dst, int e) {
    int i = blockIdx.x * blockDim.x + threadIdx.x;
    if (i < e) {
        int d = dst[i];
        int p = atomicAdd(&g_cur[d], 1);
        g_col[p] = src[i];
    }
}

// ---------------- per-node GEMM: y = dinv * (x @ W) ----------------
// TPN threads cooperate per node; each computes FO/TPN output features.
template <int FI, int FO, int TPN>
__global__ void k_gemm(const float* __restrict__ x, const float* __restrict__ W,
                       float* __restrict__ y, int n) {
    __shared__ float sW[FI * FO];
    for (int i = threadIdx.x; i < FI * FO; i += blockDim.x) sW[i] = W[i];
    __syncthreads();

    int gidx = blockIdx.x * blockDim.x + threadIdx.x;
    int node = gidx / TPN;
    int sub  = gidx % TPN;
    if (node >= n) return;

    constexpr int FOT = FO / TPN;
    float acc[FOT];
    #pragma unroll
    for (int j = 0; j < FOT; j++) acc[j] = 0.f;

    const float* xr = x + (size_t)node * FI;
    #pragma unroll
    for (int k = 0; k < FI; k++) {
        float xv = xr[k];
        const float* wr = sW + k * FO + sub * FOT;
        #pragma unroll
        for (int j = 0; j < FOT; j++) acc[j] += xv * wr[j];
    }
    float di = g_dinv[node];
    float* yr = y + (size_t)node * FO + sub * FOT;
    #pragma unroll
    for (int j = 0; j < FOT; j++) yr[j] = di * acc[j];
}

// ---------------- aggregate: out = relu(dinv*(y[node] + sum_nbr y[src]) + b) ----------------
template <int F>
__global__ void k_agg(const float* __restrict__ yb, const float* __restrict__ b,
                      float* __restrict__ out, int n) {
    constexpr int T = F / 4;               // threads per node (float4 per thread)
    int tid = threadIdx.x;
    int g = tid / T, lane = tid % T;
    int node = blockIdx.x * (blockDim.x / T) + g;
    if (node >= n) return;

    const float4* yv = (const float4*)yb;
    float4 acc = yv[(size_t)node * T + lane];   // self-loop term (y = dinv*h already)
    int start = g_row[node];
    int cnt = g_cnt[node];
    for (int e = 0; e < cnt; e++) {
        int s = g_col[start + e];
        float4 v = yv[(size_t)s * T + lane];
        acc.x += v.x; acc.y += v.y; acc.z += v.z; acc.w += v.w;
    }
    float di = g_dinv[node];
    float4 bv = ((const float4*)b)[lane];
    float4 o;
    o.x = fmaxf(di * acc.x + bv.x, 0.f);
    o.y = fmaxf(di * acc.y + bv.y, 0.f);
    o.z = fmaxf(di * acc.z + bv.z, 0.f);
    o.w = fmaxf(di * acc.w + bv.w, 0.f);
    ((float4*)out)[(size_t)node * T + lane] = o;
}

// ---------------- layer3 aggregate + fused FC (64x64) ----------------
__global__ void k_agg64_fc(const float* __restrict__ yb, const float* __restrict__ b3,
                           const float* __restrict__ Wfc, const float* __restrict__ bfc,
                           float* __restrict__ out, int n) {
    constexpr int T = 16;                  // threads per node, float4 each -> 64 feats
    __shared__ float4 sW[64 * 16];         // Wfc rows as float4 (16 KB)
    __shared__ float  sh[16][65];          // h3 rows, padded against bank conflicts

    int tid = threadIdx.x;
    for (int i = tid; i < 64 * 16; i += 256) sW[i] = ((const float4*)Wfc)[i];

    int g = tid / T, lane = tid % T;
    int node = blockIdx.x * 16 + g;

    if (node < n) {
        const float4* yv = (const float4*)yb;
        float4 acc = yv[(size_t)node * T + lane];
        int start = g_row[node];
        int cnt = g_cnt[node];
        for (int e = 0; e < cnt; e++) {
            int s = g_col[start + e];
            float4 v = yv[(size_t)s * T + lane];
            acc.x += v.x; acc.y += v.y; acc.z += v.z; acc.w += v.w;
        }
        float di = g_dinv[node];
        float4 bv = ((const float4*)b3)[lane];
        sh[g][lane * 4 + 0] = fmaxf(di * acc.x + bv.x, 0.f);
        sh[g][lane * 4 + 1] = fmaxf(di * acc.y + bv.y, 0.f);
        sh[g][lane * 4 + 2] = fmaxf(di * acc.z + bv.z, 0.f);
        sh[g][lane * 4 + 3] = fmaxf(di * acc.w + bv.w, 0.f);
    }
    __syncthreads();

    if (node < n) {
        float4 o = ((const float4*)bfc)[lane];
        #pragma unroll
        for (int k = 0; k < 64; k++) {
            float hv = sh[g][k];
            float4 w = sW[k * 16 + lane];
            o.x += hv * w.x; o.y += hv * w.y; o.z += hv * w.z; o.w += hv * w.w;
        }
        ((float4*)out)[(size_t)node * T + lane] = o;
    }
}

// ---------------- launch ----------------

extern "C" void kernel_launch(void* const* d_in, const int* in_sizes, int n_in,
                              void* d_out, int out_size) {
    const float* x   = (const float*)d_in[0];
    const float* W1  = (const float*)d_in[1];
    const float* b1  = (const float*)d_in[2];
    const float* W2  = (const float*)d_in[3];
    const float* b2  = (const float*)d_in[4];
    const float* W3  = (const float*)d_in[5];
    const float* b3  = (const float*)d_in[6];
    const float* Wfc = (const float*)d_in[7];
    const float* bfc = (const float*)d_in[8];
    const int*   ei  = (const int*)d_in[9];

    int n = in_sizes[0] / 8;         // nodes
    int e = in_sizes[9] / 2;         // edges
    const int* src = ei;
    const int* dst = ei + e;
    float* out = (float*)d_out;

    float *yb, *bufA, *bufB;
    cudaGetSymbolAddress((void**)&yb,   g_y);
    cudaGetSymbolAddress((void**)&bufA, g_bufA);
    cudaGetSymbolAddress((void**)&bufB, g_bufB);

    // CSR build
    k_zero<<<(n + 255) / 256, 256>>>(n);
    k_hist<<<(e + 255) / 256, 256>>>(dst, e);
    k_scan1<<<(n + 511) / 512, 512>>>(n);
    k_scan2<<<1, 512>>>();
    k_fin<<<(n + 255) / 256, 256>>>(n);
    k_scatter<<<(e + 255) / 256, 256>>>(src, dst, e);

    // Layer 1: 8 -> 16
    k_gemm<8, 16, 1><<<(n + 255) / 256, 256>>>(x, W1, yb, n);
    k_agg<16><<<(n + 63) / 64, 256>>>(yb, b1, bufA, n);

    // Layer 2: 16 -> 32
    k_gemm<16, 32, 1><<<(n + 255) / 256, 256>>>(bufA, W2, yb, n);
    k_agg<32><<<(n + 31) / 32, 256>>>(yb, b2, bufB, n);

    // Layer 3: 32 -> 64, aggregate fused with FC 64x64
    k_gemm<32, 64, 2><<<(2 * n + 255) / 256, 256>>>(bufB, W3, yb, n);
    k_agg64_fc<<<(n + 15) / 16, 256>>>(yb, b3, Wfc, bfc, out, n);
}

// round 2
// speedup vs baseline: 1.0283x; 1.0283x over previous
#include <cuda_runtime.h>
#include <math.h>

#define NODES 262144
#define EDGES 2097152

// Scratch (device globals — no runtime allocation allowed)
__device__ __align__(16) float g_y0[NODES * 8];   // dinv * x           (layer1 gather src)
__device__ __align__(16) float g_y1[NODES * 16];  // dinv * relu(h1)    (layer2 gather src)
__device__ __align__(16) float g_y2[NODES * 32];  // dinv * relu(h2)    (layer3 gather src)
__device__ int   g_cnt[NODES];     // in-degree counts (excl self loop)
__device__ int   g_row[NODES];     // CSR row offsets
__device__ int   g_cur[NODES];     // scatter cursors
__device__ float g_dinv[NODES];    // rsqrt(deg+1)
__device__ int   g_col[EDGES];     // CSR column (src) indices
__device__ int   g_bsum[512];      // block sums for scan

// ---------------- CSR build ----------------

__global__ void k_zero(int n) {
    int i = blockIdx.x * blockDim.x + threadIdx.x;
    if (i < n) g_cnt[i] = 0;
}

__global__ void k_hist(const int* __restrict__ dst, int e) {
    int i = blockIdx.x * blockDim.x + threadIdx.x;
    if (i < e) atomicAdd(&g_cnt[dst[i]], 1);
}

__global__ void k_scan1(int n) {
    __shared__ int s[512];
    int t = threadIdx.x;
    int idx = blockIdx.x * 512 + t;
    int v = (idx < n) ? g_cnt[idx] : 0;
    s[t] = v;
    __syncthreads();
    #pragma unroll
    for (int off = 1; off < 512; off <<= 1) {
        int a = (t >= off) ? s[t - off] : 0;
        __syncthreads();
        s[t] += a;
        __syncthreads();
    }
    if (idx < n) g_row[idx] = s[t] - v;           // exclusive within block
    if (t == 511) g_bsum[blockIdx.x] = s[511];    // block total
}

__global__ void k_scan2() {
    __shared__ int s[512];
    int t = threadIdx.x;
    int v = g_bsum[t];
    s[t] = v;
    __syncthreads();
    #pragma unroll
    for (int off = 1; off < 512; off <<= 1) {
        int a = (t >= off) ? s[t - off] : 0;
        __syncthreads();
        s[t] += a;
        __syncthreads();
    }
    g_bsum[t] = s[t] - v;                         // exclusive block offsets
}

// finalize row offsets + dinv, and emit y0 = dinv * x (layer1 gather source)
__global__ void k_fin(const float* __restrict__ x, int n) {
    int i = blockIdx.x * blockDim.x + threadIdx.x;
    if (i < n) {
        int r = g_row[i] + g_bsum[i >> 9];
        g_row[i] = r;
        g_cur[i] = r;
        float di = rsqrtf((float)(g_cnt[i] + 1));
        g_dinv[i] = di;
        float4 a = ((const float4*)x)[i * 2];
        float4 b = ((const float4*)x)[i * 2 + 1];
        a.x *= di; a.y *= di; a.z *= di; a.w *= di;
        b.x *= di; b.y *= di; b.z *= di; b.w *= di;
        ((float4*)g_y0)[i * 2]     = a;
        ((float4*)g_y0)[i * 2 + 1] = b;
    }
}

__global__ void k_scatter(const int* __restrict__ src, const int* __restrict__ dst, int e) {
    int i = blockIdx.x * blockDim.x + threadIdx.x;
    if (i < e) {
        int d = dst[i];
        int p = atomicAdd(&g_cur[d], 1);
        g_col[p] = src[i];
    }
}

// ---------------- fused layer: warp-per-node ----------------
// agg[f] = dinv * (yin[node][f] + sum_{src} yin[src][f])   (yin pre-scaled by dinv)
// h      = relu(agg @ W + b)
// yout   = dinv * h        (ready as next layer's gather source)
template <int F, int FO>
__global__ void k_layer(const float* __restrict__ yin, const float* __restrict__ W,
                        const float* __restrict__ b, float* __restrict__ yout, int n) {
    __shared__ float sW[F * FO];
    for (int i = threadIdx.x; i < F * FO; i += blockDim.x) sW[i] = W[i];
    __syncthreads();

    int node = (blockIdx.x * blockDim.x + threadIdx.x) >> 5;
    int lane = threadIdx.x & 31;
    if (node >= n) return;

    int start = g_row[node];
    int cnt   = g_cnt[node];
    float di  = g_dinv[node];

    constexpr int EP = 32 / F;        // edges processed per warp iteration
    int f  = lane & (F - 1);
    int eo = lane / F;

    float acc = (lane < F) ? yin[(size_t)node * F + lane] : 0.f;   // self term
    int e = eo;
    for (; e + EP < cnt; e += 2 * EP) {
        int s0 = g_col[start + e];
        int s1 = g_col[start + e + EP];
        acc += yin[(size_t)s0 * F + f] + yin[(size_t)s1 * F + f];
    }
    if (e < cnt) acc += yin[(size_t)g_col[start + e] * F + f];

    #pragma unroll
    for (int off = F; off < 32; off <<= 1)
        acc += __shfl_xor_sync(0xffffffffu, acc, off);
    acc *= di;                        // agg[f] in lane f (replicated)

    // in-warp GEMM: lane j computes output feature j (dup for FO < 32)
    int j = lane % FO;
    float o = b[j];
    #pragma unroll
    for (int k = 0; k < F; k++)
        o += __shfl_sync(0xffffffffu, acc, k) * sW[k * FO + j];
    o = fmaxf(o, 0.f) * di;
    if (lane < FO)
        yout[(size_t)node * FO + lane] = o;
}

// ---------------- layer3 (32->64) fused with FC (64->64) ----------------
__global__ void k_layer3(const float* __restrict__ yin, const float* __restrict__ W3,
                         const float* __restrict__ b3, const float* __restrict__ Wfc,
                         const float* __restrict__ bfc, float* __restrict__ out, int n) {
    __shared__ float sW3[32 * 64];    // 8 KB
    __shared__ float sWfc[64 * 64];   // 16 KB
    for (int i = threadIdx.x; i < 32 * 64; i += blockDim.x) sW3[i] = W3[i];
    for (int i = threadIdx.x; i < 64 * 64; i += blockDim.x) sWfc[i] = Wfc[i];
    __syncthreads();

    int node = (blockIdx.x * blockDim.x + threadIdx.x) >> 5;
    int lane = threadIdx.x & 31;
    if (node >= n) return;

    int start = g_row[node];
    int cnt   = g_cnt[node];
    float di  = g_dinv[node];

    // aggregate 32-wide rows: whole warp reads one 128B row per edge
    float acc = yin[(size_t)node * 32 + lane];
    int e = 0;
    for (; e + 3 < cnt; e += 4) {
        int s0 = g_col[start + e];
        int s1 = g_col[start + e + 1];
        int s2 = g_col[start + e + 2];
        int s3 = g_col[start + e + 3];
        acc += yin[(size_t)s0 * 32 + lane] + yin[(size_t)s1 * 32 + lane]
             + yin[(size_t)s2 * 32 + lane] + yin[(size_t)s3 * 32 + lane];
    }
    for (; e < cnt; e++)
        acc += yin[(size_t)g_col[start + e] * 32 + lane];
    acc *= di;

    // GEMM 32 -> 64 (+b3, relu): lane computes features lane and lane+32
    float h0 = b3[lane], h1 = b3[lane + 32];
    #pragma unroll
    for (int k = 0; k < 32; k++) {
        float a = __shfl_sync(0xffffffffu, acc, k);
        h0 += a * sW3[k * 64 + lane];
        h1 += a * sW3[k * 64 + lane + 32];
    }
    h0 = fmaxf(h0, 0.f);
    h1 = fmaxf(h1, 0.f);

    // FC 64 -> 64 (+bfc)
    float o0 = bfc[lane], o1 = bfc[lane + 32];
    #pragma unroll
    for (int k = 0; k < 32; k++) {
        float a = __shfl_sync(0xffffffffu, h0, k);
        float c = __shfl_sync(0xffffffffu, h1, k);
        o0 += a * sWfc[k * 64 + lane]      + c * sWfc[(k + 32) * 64 + lane];
        o1 += a * sWfc[k * 64 + lane + 32] + c * sWfc[(k + 32) * 64 + lane + 32];
    }
    out[(size_t)node * 64 + lane]      = o0;
    out[(size_t)node * 64 + lane + 32] = o1;
}

// ---------------- launch ----------------

extern "C" void kernel_launch(void* const* d_in, const int* in_sizes, int n_in,
                              void* d_out, int out_size) {
    const float* x   = (const float*)d_in[0];
    const float* W1  = (const float*)d_in[1];
    const float* b1  = (const float*)d_in[2];
    const float* W2  = (const float*)d_in[3];
    const float* b2  = (const float*)d_in[4];
    const float* W3  = (const float*)d_in[5];
    const float* b3  = (const float*)d_in[6];
    const float* Wfc = (const float*)d_in[7];
    const float* bfc = (const float*)d_in[8];
    const int*   ei  = (const int*)d_in[9];

    int n = in_sizes[0] / 8;         // nodes
    int e = in_sizes[9] / 2;         // edges
    const int* src = ei;
    const int* dst = ei + e;
    float* out = (float*)d_out;

    float *y0, *y1, *y2;
    cudaGetSymbolAddress((void**)&y0, g_y0);
    cudaGetSymbolAddress((void**)&y1, g_y1);
    cudaGetSymbolAddress((void**)&y2, g_y2);

    // CSR build (+ y0 = dinv*x emitted in k_fin)
    k_zero<<<(n + 255) / 256, 256>>>(n);
    k_hist<<<(e + 255) / 256, 256>>>(dst, e);
    k_scan1<<<(n + 511) / 512, 512>>>(n);
    k_scan2<<<1, 512>>>();
    k_fin<<<(n + 255) / 256, 256>>>(x, n);
    k_scatter<<<(e + 255) / 256, 256>>>(src, dst, e);

    int wgrid = (n * 32 + 255) / 256;   // warp-per-node kernels

    // Layer 1: aggregate@8 -> GEMM 8->16 -> relu -> scale
    k_layer<8, 16><<<wgrid, 256>>>(y0, W1, b1, y1, n);
    // Layer 2: aggregate@16 -> GEMM 16->32 -> relu -> scale
    k_layer<16, 32><<<wgrid, 256>>>(y1, W2, b2, y2, n);
    // Layer 3: aggregate@32 -> GEMM 32->64 -> relu -> FC 64->64
    k_layer3<<<wgrid, 256>>>(y2, W3, b3, Wfc, bfc, out, n);
}

// round 3
// speedup vs baseline: 1.4422x; 1.4025x over previous
#include <cuda_runtime.h>
#include <math.h>

#define NODES 262144
#define EDGES 2097152

// Scratch (device globals — no runtime allocation allowed)
__device__ __align__(16) float g_y0[NODES * 8];   // dinv * x           (layer1 gather src)
__device__ __align__(16) float g_y1[NODES * 16];  // dinv * relu(h1)    (layer2 gather src)
__device__ __align__(16) float g_y2[NODES * 32];  // dinv * relu(h2)    (layer3 gather src)
__device__ int   g_cnt[NODES];
__device__ int   g_row[NODES];
__device__ int   g_cur[NODES];
__device__ float g_dinv[NODES];
__device__ int   g_col[EDGES];
__device__ int   g_bsum[512];

// ---------------- CSR build ----------------

__global__ void k_hist(const int* __restrict__ dst, int e) {
    int i = blockIdx.x * blockDim.x + threadIdx.x;
    if (i < e) atomicAdd(&g_cnt[dst[i]], 1);
}

__global__ void k_scan1(int n) {
    __shared__ int s[512];
    int t = threadIdx.x;
    int idx = blockIdx.x * 512 + t;
    int v = (idx < n) ? g_cnt[idx] : 0;
    s[t] = v;
    __syncthreads();
    #pragma unroll
    for (int off = 1; off < 512; off <<= 1) {
        int a = (t >= off) ? s[t - off] : 0;
        __syncthreads();
        s[t] += a;
        __syncthreads();
    }
    if (idx < n) g_row[idx] = s[t] - v;           // exclusive within block
    if (t == 511) g_bsum[blockIdx.x] = s[511];    // block total
}

// fused: block-sum prefix (redundant per-block reduction) + row/cur/dinv finalize + y0 = dinv*x
__global__ void k_scan2fin(const float* __restrict__ x, int n) {
    __shared__ int s[512];
    int b = blockIdx.x, t = threadIdx.x;
    s[t] = (t < b) ? g_bsum[t] : 0;
    __syncthreads();
    #pragma unroll
    for (int off = 256; off > 0; off >>= 1) {
        if (t < off) s[t] += s[t + off];
        __syncthreads();
    }
    int offset = s[0];
    int i = b * 512 + t;
    if (i < n) {
        int r = g_row[i] + offset;
        g_row[i] = r;
        g_cur[i] = r;
        float di = rsqrtf((float)(g_cnt[i] + 1));
        g_dinv[i] = di;
        float4 a = ((const float4*)x)[i * 2];
        float4 c = ((const float4*)x)[i * 2 + 1];
        a.x *= di; a.y *= di; a.z *= di; a.w *= di;
        c.x *= di; c.y *= di; c.z *= di; c.w *= di;
        ((float4*)g_y0)[i * 2]     = a;
        ((float4*)g_y0)[i * 2 + 1] = c;
    }
}

__global__ void k_scatter(const int* __restrict__ src, const int* __restrict__ dst, int e) {
    int i = blockIdx.x * blockDim.x + threadIdx.x;
    if (i < e) {
        int d = dst[i];
        int p = atomicAdd(&g_cur[d], 1);
        g_col[p] = src[i];
    }
}

// ---------------- layer 1: agg@8 -> GEMM 8->16 -> relu -> scale (warp per node) ----------------
__global__ void k_layer1(const float* __restrict__ yin, const float* __restrict__ W,
                         const float* __restrict__ b, float* __restrict__ yout, int n) {
    __shared__ float sW[8 * 16];
    if (threadIdx.x < 128) sW[threadIdx.x] = W[threadIdx.x];
    __syncthreads();

    int node = (blockIdx.x * blockDim.x + threadIdx.x) >> 5;
    int lane = threadIdx.x & 31;
    if (node >= n) return;

    int start = g_row[node];
    int cnt   = g_cnt[node];
    float di  = g_dinv[node];

    int f  = lane & 7;
    int eo = lane >> 3;                 // 4 edge groups

    float acc = (lane < 8) ? yin[(size_t)node * 8 + lane] : 0.f;
    int e = eo;
    for (; e + 4 < cnt; e += 8) {
        int s0 = g_col[start + e];
        int s1 = g_col[start + e + 4];
        acc += yin[(size_t)s0 * 8 + f] + yin[(size_t)s1 * 8 + f];
    }
    if (e < cnt) acc += yin[(size_t)g_col[start + e] * 8 + f];

    acc += __shfl_xor_sync(0xffffffffu, acc, 8);
    acc += __shfl_xor_sync(0xffffffffu, acc, 16);
    acc *= di;                          // lane f holds agg[f], replicated over groups

    // split-k GEMM: lane -> (j = lane%16, half = lane/16 handles k in [4h, 4h+4))
    int j = lane & 15, half = lane >> 4;
    float o = 0.f;
    #pragma unroll
    for (int kk = 0; kk < 4; kk++) {
        int k = half * 4 + kk;
        o += __shfl_sync(0xffffffffu, acc, k) * sW[k * 16 + j];
    }
    o += __shfl_xor_sync(0xffffffffu, o, 16);
    if (lane < 16)
        yout[(size_t)node * 16 + lane] = fmaxf(o + b[lane], 0.f) * di;
}

// ---------------- layer 2: agg@16 -> GEMM 16->32 -> relu -> scale (warp per node) -------------
__global__ void k_layer2(const float* __restrict__ yin, const float* __restrict__ W,
                         const float* __restrict__ b, float* __restrict__ yout, int n) {
    __shared__ float sW[16 * 32];
    for (int i = threadIdx.x; i < 512; i += blockDim.x) sW[i] = W[i];
    __syncthreads();

    int node = (blockIdx.x * blockDim.x + threadIdx.x) >> 5;
    int lane = threadIdx.x & 31;
    if (node >= n) return;

    int start = g_row[node];
    int cnt   = g_cnt[node];
    float di  = g_dinv[node];

    int f  = lane & 15;
    int eo = lane >> 4;                 // 2 edge groups

    float acc = (lane < 16) ? yin[(size_t)node * 16 + lane] : 0.f;
    int e = eo;
    for (; e + 2 < cnt; e += 4) {
        int s0 = g_col[start + e];
        int s1 = g_col[start + e + 2];
        acc += yin[(size_t)s0 * 16 + f] + yin[(size_t)s1 * 16 + f];
    }
    if (e < cnt) acc += yin[(size_t)g_col[start + e] * 16 + f];

    acc += __shfl_xor_sync(0xffffffffu, acc, 16);
    acc *= di;

    float o = b[lane];
    #pragma unroll
    for (int k = 0; k < 16; k++)
        o += __shfl_sync(0xffffffffu, acc, k) * sW[k * 32 + lane];
    yout[(size_t)node * 32 + lane] = fmaxf(o, 0.f) * di;
}

// ---------------- layer 3 + FC: block of 256 handles 32 nodes ----------------
// agg@32 (warp per node, 4 nodes/warp) -> register-tiled GEMM 32->64 (relu) -> GEMM 64->64
__global__ __launch_bounds__(256) void k_l3fc(
        const float* __restrict__ yin, const float* __restrict__ W3,
        const float* __restrict__ b3, const float* __restrict__ Wfc,
        const float* __restrict__ bfc, float* __restrict__ out, int n) {
    __shared__ float sW3[32 * 64];      // 8 KB   [k][j]
    __shared__ float sWfc[64 * 64];     // 16 KB  [k][j]
    __shared__ float sAgg[32][33];      // 4.2 KB [node][k]
    __shared__ float sH[32][65];        // 8.3 KB [node][k]

    int tid = threadIdx.x;
    for (int i = tid; i < 32 * 64; i += 256) sW3[i] = W3[i];
    for (int i = tid; i < 64 * 64; i += 256) sWfc[i] = Wfc[i];

    int node0 = blockIdx.x * 32;
    int warp  = tid >> 5;
    int lane  = tid & 31;

    // ---- aggregation: each warp handles 4 nodes; lane = feature ----
    #pragma unroll
    for (int r = 0; r < 4; r++) {
        int ln = warp * 4 + r;
        int node = node0 + ln;
        float acc = 0.f;
        if (node < n) {
            int start = g_row[node];
            int cnt   = g_cnt[node];
            float di  = g_dinv[node];
            acc = yin[(size_t)node * 32 + lane];
            int e = 0;
            for (; e + 3 < cnt; e += 4) {
                int s0 = g_col[start + e];
                int s1 = g_col[start + e + 1];
                int s2 = g_col[start + e + 2];
                int s3 = g_col[start + e + 3];
                acc += yin[(size_t)s0 * 32 + lane] + yin[(size_t)s1 * 32 + lane]
                     + yin[(size_t)s2 * 32 + lane] + yin[(size_t)s3 * 32 + lane];
            }
            for (; e < cnt; e++)
                acc += yin[(size_t)g_col[start + e] * 32 + lane];
            acc *= di;
        }
        sAgg[ln][lane] = acc;
    }
    __syncthreads();

    // ---- GEMM1: H[32x64] = relu(AGG[32x32] @ W3 + b3) ----
    int r0 = (tid >> 4) * 2;            // 2 rows per thread
    int c0 = (tid & 15) * 4;            // 4 cols per thread
    float acc0[4], acc1[4];
    {
        float4 bv = *(const float4*)&b3[c0];
        acc0[0] = bv.x; acc0[1] = bv.y; acc0[2] = bv.z; acc0[3] = bv.w;
        acc1[0] = bv.x; acc1[1] = bv.y; acc1[2] = bv.z; acc1[3] = bv.w;
    }
    #pragma unroll
    for (int k = 0; k < 32; k++) {
        float a0 = sAgg[r0][k];
        float a1 = sAgg[r0 + 1][k];
        float4 w = *(const float4*)&sW3[k * 64 + c0];
        acc0[0] += a0 * w.x; acc0[1] += a0 * w.y; acc0[2] += a0 * w.z; acc0[3] += a0 * w.w;
        acc1[0] += a1 * w.x; acc1[1] += a1 * w.y; acc1[2] += a1 * w.z; acc1[3] += a1 * w.w;
    }
    #pragma unroll
    for (int j = 0; j < 4; j++) {
        sH[r0][c0 + j]     = fmaxf(acc0[j], 0.f);
        sH[r0 + 1][c0 + j] = fmaxf(acc1[j], 0.f);
    }
    __syncthreads();

    // ---- GEMM2: OUT[32x64] = H[32x64] @ Wfc + bfc ----
    {
        float4 bv = *(const float4*)&bfc[c0];
        acc0[0] = bv.x; acc0[1] = bv.y; acc0[2] = bv.z; acc0[3] = bv.w;
        acc1[0] = bv.x; acc1[1] = bv.y; acc1[2] = bv.z; acc1[3] = bv.w;
    }
    #pragma unroll
    for (int k = 0; k < 64; k++) {
        float a0 = sH[r0][k];
        float a1 = sH[r0 + 1][k];
        float4 w = *(const float4*)&sWfc[k * 64 + c0];
        acc0[0] += a0 * w.x; acc0[1] += a0 * w.y; acc0[2] += a0 * w.z; acc0[3] += a0 * w.w;
        acc1[0] += a1 * w.x; acc1[1] += a1 * w.y; acc1[2] += a1 * w.z; acc1[3] += a1 * w.w;
    }
    int nodeA = node0 + r0, nodeB = node0 + r0 + 1;
    if (nodeA < n) {
        float4 o; o.x = acc0[0]; o.y = acc0[1]; o.z = acc0[2]; o.w = acc0[3];
        *(float4*)&out[(size_t)nodeA * 64 + c0] = o;
    }
    if (nodeB < n) {
        float4 o; o.x = acc1[0]; o.y = acc1[1]; o.z = acc1[2]; o.w = acc1[3];
        *(float4*)&out[(size_t)nodeB * 64 + c0] = o;
    }
}

// ---------------- launch ----------------

extern "C" void kernel_launch(void* const* d_in, const int* in_sizes, int n_in,
                              void* d_out, int out_size) {
    const float* x   = (const float*)d_in[0];
    const float* W1  = (const float*)d_in[1];
    const float* b1  = (const float*)d_in[2];
    const float* W2  = (const float*)d_in[3];
    const float* b2  = (const float*)d_in[4];
    const float* W3  = (const float*)d_in[5];
    const float* b3  = (const float*)d_in[6];
    const float* Wfc = (const float*)d_in[7];
    const float* bfc = (const float*)d_in[8];
    const int*   ei  = (const int*)d_in[9];

    int n = in_sizes[0] / 8;
    int e = in_sizes[9] / 2;
    const int* src = ei;
    const int* dst = ei + e;
    float* out = (float*)d_out;

    float *y0, *y1, *y2;
    int* cntp;
    cudaGetSymbolAddress((void**)&y0, g_y0);
    cudaGetSymbolAddress((void**)&y1, g_y1);
    cudaGetSymbolAddress((void**)&y2, g_y2);
    cudaGetSymbolAddress((void**)&cntp, g_cnt);

    cudaMemsetAsync(cntp, 0, (size_t)n * sizeof(int));

    k_hist<<<(e + 255) / 256, 256>>>(dst, e);
    k_scan1<<<(n + 511) / 512, 512>>>(n);
    k_scan2fin<<<(n + 511) / 512, 512>>>(x, n);
    k_scatter<<<(e + 255) / 256, 256>>>(src, dst, e);

    int wgrid = (n * 32 + 255) / 256;
    k_layer1<<<wgrid, 256>>>(y0, W1, b1, y1, n);
    k_layer2<<<wgrid, 256>>>(y1, W2, b2, y2, n);
    k_l3fc<<<(n + 31) / 32, 256>>>(y2, W3, b3, Wfc, bfc, out, n);
}